// round 15
// baseline (speedup 1.0000x reference)
#include <cuda_runtime.h>
#include <cuda_fp16.h>
#include <cuda_bf16.h>
#include <math.h>

// Problem constants (match reference_code)
#define HH 256
#define WW 336
#define HWPIX (HH * WW)            // 86016
#define BB 8
#define NEV 262144
#define FLOW_SCALING 336.0f
#define REG_WEIGHT 0.001f

// ---------------------------------------------------------------------------
// Accumulator: 16B "quad" entries, 4 parity-shifted copies (see R6 derivation).
// Quad (16B) = 4 cells f16x2 {iwe, iwe_ts}:
//   lane0=(y0,x0) lane1=(y0,x0+1) lane2=(y0+1,x0) lane3=(y0+1,x0+1)
// Copy (cy,cx): quad(j,k) covers rows 2j-cy..2j-cy+1, cols 2k-cx..2k-cx+1.
// Bilinear block (ty..ty+1, lx..lx+1) -> ONE aligned quad in copy (ty&1, lx&1).
// Cleared by cudaMemsetAsync each run (self-clear raced/regressed: R12, R14 note).
// ---------------------------------------------------------------------------
#define NPLANES 32                 // b(8) x tref(2) x p(2)
#define RP 130
#define XP 170
#define COPY_ENT ((size_t)RP * XP)            // 22100 quads
#define PLANE_ENT (4 * COPY_ENT)              // 88400 quads
#define NQUAD ((size_t)NPLANES * PLANE_ENT)   // ~45MB

#define NULL_WORDS (NQUAD * 2)
__device__ __align__(16) unsigned long long g_acc[NULL_WORDS + 2];

#define G_LOSS_PTR (reinterpret_cast<double*>(&g_acc[NULL_WORDS]))
#define G_CTR_PTR  (reinterpret_cast<unsigned int*>(&g_acc[NULL_WORDS + 1]))

__device__ __forceinline__ void red_quad(void* entry,
                                         __half2 a, __half2 b, __half2 c, __half2 d) {
    unsigned int ua = *reinterpret_cast<unsigned int*>(&a);
    unsigned int ub = *reinterpret_cast<unsigned int*>(&b);
    unsigned int uc = *reinterpret_cast<unsigned int*>(&c);
    unsigned int ud = *reinterpret_cast<unsigned int*>(&d);
    asm volatile("red.global.add.noftz.v4.f16x2 [%0], {%1, %2, %3, %4};"
                 :: "l"(entry), "r"(ua), "r"(ub), "r"(uc), "r"(ud) : "memory");
}

// ---------------------------------------------------------------------------
// Block reduction helper (f32 partials -> double atomic)
// ---------------------------------------------------------------------------
__device__ __forceinline__ void block_reduce_add(float v) {
    __shared__ float sdata[32];
    const int lane = threadIdx.x & 31;
    const int warp = threadIdx.x >> 5;
#pragma unroll
    for (int off = 16; off > 0; off >>= 1)
        v += __shfl_down_sync(0xffffffffu, v, off);
    if (lane == 0) sdata[warp] = v;
    __syncthreads();
    if (warp == 0) {
        const int nwarps = (blockDim.x + 31) >> 5;
        float s = (lane < nwarps) ? sdata[lane] : 0.0f;
#pragma unroll
        for (int off = 16; off > 0; off >>= 1)
            s += __shfl_down_sync(0xffffffffu, s, off);
        if (lane == 0) atomicAdd(G_LOSS_PTR, (double)s);
    }
}

// ---------------------------------------------------------------------------
// Scatter one event (2 trefs x one 16B v4 red each).
// ---------------------------------------------------------------------------
__device__ __forceinline__ void scatter_event(const float4 e, int b,
                                              float dxf, float dyf) {
    const float ts = e.x;
    const float yy = e.y;
    const float xx = e.z;
    const int   p  = (e.w > 0.0f) ? 0 : 1;   // pol_mask: col0=(pol==1), col1=(pol==0)

    const float wy0b = fmaf(-ts, dyf, yy);
    const float wx0b = fmaf(-ts, dxf, xx);

#pragma unroll
    for (int tref = 0; tref < 2; ++tref) {
        const float wy = tref ? (wy0b + dyf) : wy0b;
        const float wx = tref ? (wx0b + dxf) : wx0b;
        const float tg = tref ? ts : (1.0f - ts);

        const float tyf = floorf(wy);
        const float lxf = floorf(wx);
        const int ty = (int)tyf;
        const int lx = (int)lxf;
        const float fry = wy - tyf;
        const float frx = wx - lxf;

        const float wy0 = ((unsigned)ty       < HH) ? (1.0f - fry) : 0.0f;
        const float wy1 = ((unsigned)(ty + 1) < HH) ? fry          : 0.0f;
        const float wxl = ((unsigned)lx       < WW) ? (1.0f - frx) : 0.0f;
        const float wxr = ((unsigned)(lx + 1) < WW) ? frx          : 0.0f;

        if ((wy0 + wy1) * (wxl + wxr) == 0.0f) continue;

        const int tyc = min(max(ty, -1), HH - 1);
        const int lxc = min(max(lx, -1), WW - 1);

        const int cy = tyc & 1;
        const int cx = lxc & 1;
        const int j  = (tyc + cy) >> 1;
        const int k  = (lxc + cx) >> 1;
        const int plane = ((b * 2 + tref) * 2 + p);

        const size_t entry = (size_t)plane * PLANE_ENT
                           + (size_t)(cy * 2 + cx) * COPY_ENT
                           + (size_t)j * XP + k;

        const float w00 = wy0 * wxl, w01 = wy0 * wxr;
        const float w10 = wy1 * wxl, w11 = wy1 * wxr;

        red_quad(reinterpret_cast<char*>(g_acc) + entry * 16,
                 __floats2half2_rn(w00, w00 * tg),
                 __floats2half2_rn(w01, w01 * tg),
                 __floats2half2_rn(w10, w10 * tg),
                 __floats2half2_rn(w11, w11 * tg));
    }
}

// ---------------------------------------------------------------------------
// Scatter: grid (512, 8) x 256. TWO events per thread (split-half indexing,
// both streams fully coalesced) for doubled MLP. Then the flow-smoothness
// reduction rides along on this kernel's 1.05M threads (its FP pipes are
// otherwise idle) -- removes Phase B from the reduce kernel.
// ---------------------------------------------------------------------------
#define HALF_NEV (NEV / 2)

__global__ void __launch_bounds__(256) scatter_kernel(
    const float* __restrict__ flow,       // [B,2,H,W]
    const float* __restrict__ event_list) // [B,N,4] = {t, y, x, pol(+-1)}
{
    const int t = blockIdx.x * 256 + threadIdx.x;   // [0, HALF_NEV)
    const int b = blockIdx.y;

    const float4* ev = reinterpret_cast<const float4*>(event_list) + (size_t)b * NEV;
    const float4 e0 = ev[t];
    const float4 e1 = ev[t + HALF_NEV];

    const float* fb = flow + (size_t)b * 2 * HWPIX;
    const int pix0 = (int)e0.y * WW + (int)e0.z;
    const int pix1 = (int)e1.y * WW + (int)e1.z;
    const float dxf0 = __ldg(fb + pix0) * FLOW_SCALING;
    const float dxf1 = __ldg(fb + pix1) * FLOW_SCALING;
    const float dyf0 = __ldg(fb + HWPIX + pix0) * FLOW_SCALING;
    const float dyf1 = __ldg(fb + HWPIX + pix1) * FLOW_SCALING;

    scatter_event(e0, b, dxf0, dyf0);
    scatter_event(e1, b, dxf1, dyf1);

    // ---- Smoothness: REG_WEIGHT * sum sqrt(d^2+1e-6) over flow dx & dy ----
    float ssum = 0.0f;
    const int total_flow = BB * 2 * HWPIX;        // 1,376,256
    const int nthreads = 512 * 8 * 256;           // 1,048,576
    const int gtid = (b * 512 + blockIdx.x) * 256 + threadIdx.x;
    for (int i = gtid; i < total_flow; i += nthreads) {
        const int o = i % HWPIX;
        const int h = o / WW;
        const int w = o % WW;
        const float v = flow[i];
        if (h < HH - 1) {
            const float d = v - flow[i + WW];
            ssum += sqrtf(d * d + 1e-6f);
        }
        if (w < WW - 1) {
            const float d = v - flow[i + 1];
            ssum += sqrtf(d * d + 1e-6f);
        }
    }
    block_reduce_add(ssum * REG_WEIGHT);
}

// ---------------------------------------------------------------------------
// Reduce: grid (2, 32, 32), block 192, 24.5KB smem (-> high occupancy).
// Block (bx, by, z): plane z, rows [8by, 8by+8), x-half [168bx, 168bx+168).
// Stage the 4 copy sub-tiles (85 quad-cols each) coalesced into smem, then
// per-cell gather + ratio^2. Last finishing block writes out[0].
// ---------------------------------------------------------------------------
#define RBX 192
#define XHW 168              // x-cells per block
#define KQ  85               // quad-cols staged per copy
#define SROW (KQ * 4)        // 340 uints per staged row
// smem bases (uints): copy0 4 rows, copy1 4 rows, copy2 5 rows, copy3 5 rows
#define SB0 0
#define SB1 (4 * SROW)       // 1360
#define SB2 (8 * SROW)       // 2720
#define SB3 (13 * SROW)      // 4420
#define STG_TOTAL (18 * SROW) // 6120 uints = 24480 B

__device__ __forceinline__ __half2 u2h(unsigned int u) {
    return *reinterpret_cast<const __half2*>(&u);
}

__global__ void __launch_bounds__(RBX) fused_reduce_kernel(float* __restrict__ out)
{
    __shared__ unsigned int stg[STG_TOTAL];
    float sum = 0.0f;

    const int j0 = blockIdx.y * 4;            // first quad-row (y0 = 8*by)
    const int kb = blockIdx.x * 84;           // first quad-col staged
    const unsigned int* __restrict__ gp =
        reinterpret_cast<const unsigned int*>(g_acc)
        + (size_t)blockIdx.z * PLANE_ENT * 4;

    // ---- Stage ----
    {
        const int      njs[4] = {4, 4, 5, 5};
        const unsigned sbs[4] = {SB0, SB1, SB2, SB3};
#pragma unroll
        for (int c = 0; c < 4; ++c) {
            const unsigned int* __restrict__ g =
                gp + (size_t)c * (COPY_ENT * 4) + (size_t)j0 * (XP * 4) + kb * 4;
            const int n4 = njs[c] * KQ;       // uint4 loads for this copy
            const unsigned sb = sbs[c];
            for (int i = threadIdx.x; i < n4; i += RBX) {
                const int jr = i / KQ;
                const int kk = i - jr * KQ;
                const uint4 v = __ldg(reinterpret_cast<const uint4*>(
                    g + (size_t)jr * (XP * 4)) + kk);
                *reinterpret_cast<uint4*>(&stg[sb + jr * SROW + kk * 4]) = v;
            }
        }
    }
    __syncthreads();

    // ---- Gather + loss ----
    const int tx = threadIdx.x;
    if (tx < XHW) {
        // local x within block; global x = kb*2 + tx (168*bx + tx)
        const unsigned xo0 = (((unsigned)tx >> 1) << 2) + (tx & 1);              // cx=0
        const unsigned xo1 = (((unsigned)(tx + 1) >> 1) << 2) + ((tx + 1) & 1);  // cx=1
#pragma unroll
        for (int r = 0; r < 8; ++r) {
            const unsigned b0 = (unsigned)(r >> 1) * SROW + ((r & 1) << 1);             // cy=0
            const unsigned b1 = (unsigned)((r + 1) >> 1) * SROW + (((r + 1) & 1) << 1); // cy=1
            const unsigned s0 = stg[SB0 + b0 + xo0];
            const unsigned s1 = stg[SB1 + b0 + xo1];
            const unsigned s2 = stg[SB2 + b1 + xo0];
            const unsigned s3 = stg[SB3 + b1 + xo1];
            const __half2 h = __hadd2(__hadd2(u2h(s0), u2h(s1)),
                                      __hadd2(u2h(s2), u2h(s3)));
            const float2 v = __half22float2(h);
            const float rt = __fdividef(v.y, v.x + 1e-9f);
            sum += rt * rt;
        }
    }

    block_reduce_add(sum);

    // Last finishing block writes the scalar (scatter's smoothness partials
    // already landed in g_loss before this kernel launched).
    __threadfence();
    if (threadIdx.x == 0) {
        const unsigned int nblocks = gridDim.x * gridDim.y * gridDim.z;
        unsigned int old = atomicAdd(G_CTR_PTR, 1u);
        if (old == nblocks - 1) {
            out[0] = (float)(*G_LOSS_PTR);
        }
    }
}

extern "C" void kernel_launch(void* const* d_in, const int* in_sizes, int n_in,
                              void* d_out, int out_size) {
    const float* flow       = (const float*)d_in[0];  // 8*2*256*336
    const float* event_list = (const float*)d_in[1];  // 8*262144*4
    // d_in[2] = pol_mask (unused; polarity derived from event_list[...,3])
    float* out = (float*)d_out;

    void* acc_ptr = nullptr;
    cudaGetSymbolAddress(&acc_ptr, g_acc);

    // Single memset clears accumulators, loss scalar, and done-counter.
    cudaMemsetAsync(acc_ptr, 0, sizeof(unsigned long long) * (NULL_WORDS + 2), 0);

    scatter_kernel<<<dim3(HALF_NEV / 256, BB), 256>>>(flow, event_list);
    fused_reduce_kernel<<<dim3(2, 32, NPLANES), RBX>>>(out);
}